// round 1
// baseline (speedup 1.0000x reference)
#include <cuda_runtime.h>
#include <cstdint>

#define FULLMASK 0xFFFFFFFFu

// Problem constants (fixed-shape problem)
constexpr int BATCH = 256;
constexpr int HID   = 16;

// tanh(x) = 1 - 2/(1 + e^{2x}), via ex2.approx + rcp.approx (2 MUFU).
// Abs err ~1e-7; saturates correctly for |x| large.
__device__ __forceinline__ float fast_tanh(float x) {
    float e;
    asm("ex2.approx.f32 %0, %1;" : "=f"(e) : "f"(x * 2.885390081777927f)); // 2*log2(e)
    float r;
    asm("rcp.approx.f32 %0, %1;" : "=f"(r) : "f"(e + 1.0f));
    return fmaf(-2.0f, r, 1.0f);
}

__global__ void __launch_bounds__(32, 1) rnn3_scan_kernel(
    const float* __restrict__ x,        // [B, T, 1]
    const float* __restrict__ prev_h0,  // [2, 16]
    const float* __restrict__ post_h0,  // [1, 1]
    const float* __restrict__ W_ih0,    // [16, 1]
    const float* __restrict__ W_hh0,    // [16, 16]
    const float* __restrict__ b_ih0,    // [16]
    const float* __restrict__ b_hh0,    // [16]
    const float* __restrict__ W_ih1,    // [16, 16]
    const float* __restrict__ W_hh1,    // [16, 16]
    const float* __restrict__ b_ih1,    // [16]
    const float* __restrict__ b_hh1,    // [16]
    const float* __restrict__ W_ihp,    // [1, 16]
    const float* __restrict__ W_hhp,    // [1, 1]
    const float* __restrict__ b_ihp,    // [1]
    const float* __restrict__ b_hhp,    // [1]
    float* __restrict__ out,            // [B, T, 1]
    int T)
{
    const int lane  = threadIdx.x;       // 0..31
    const int j     = lane & 15;         // hidden unit index
    const int base  = lane & 16;         // 0 for batch A, 16 for batch B
    const int batch = blockIdx.x * 2 + (lane >> 4);

    // ---- Register-resident weights (per lane = row j) ----
    float whh0[HID], wih1[HID], whh1[HID], wihp[HID];
#pragma unroll
    for (int k = 0; k < HID; k++) {
        whh0[k] = __ldg(&W_hh0[j * HID + k]);
        wih1[k] = __ldg(&W_ih1[j * HID + k]);
        whh1[k] = __ldg(&W_hh1[j * HID + k]);
        wihp[k] = __ldg(&W_ihp[k]);          // full vector on every lane (for redundant post dot)
    }
    const float wih0 = __ldg(&W_ih0[j]);
    const float bh0  = __ldg(&b_ih0[j]) + __ldg(&b_hh0[j]);
    const float bh1  = __ldg(&b_ih1[j]) + __ldg(&b_hh1[j]);
    const float whhp = __ldg(&W_hhp[0]);
    const float bp   = __ldg(&b_ihp[0]) + __ldg(&b_hhp[0]);

    // ---- Initial state: broadcast registers hold h[t-1] of ALL 16 units ----
    float h0b[HID], h1b[HID];
#pragma unroll
    for (int k = 0; k < HID; k++) {
        h0b[k] = __ldg(&prev_h0[k]);
        h1b[k] = __ldg(&prev_h0[HID + k]);
    }
    float y = __ldg(&post_h0[0]);

    const float* xb = x   + (size_t)batch * T;
    float*       ob = out + (size_t)batch * T;

    // 2-deep float4 prefetch pipeline for x (covers ~2 chunks ≈ 1300+ cyc of latency)
    float4 xva = *(const float4*)(xb);
    float4 xvb = *(const float4*)(xb + 4);

    for (int tc = 0; tc < T; tc += 4) {
        const float4 xv = xva;
        xva = xvb;
        if (tc + 8 < T) xvb = *(const float4*)(xb + tc + 8);

        float4 yv;
#pragma unroll
        for (int s = 0; s < 4; s++) {
            const float xt = (s == 0) ? xv.x : (s == 1) ? xv.y : (s == 2) ? xv.z : xv.w;
            const float xn = (xt + 1.0f) * 0.5f;   // min-max normalize to [0,1] scale

            // ---- layer 0: h0_j = tanh(wih0*xn + b + Whh0[j,:]·h0_prev) ----
            float s0 = fmaf(wih0, xn, bh0), s1 = 0.f, s2 = 0.f, s3 = 0.f;
#pragma unroll
            for (int k = 0; k < 4; k++) {
                s0 = fmaf(whh0[k],      h0b[k],      s0);
                s1 = fmaf(whh0[k + 4],  h0b[k + 4],  s1);
                s2 = fmaf(whh0[k + 8],  h0b[k + 8],  s2);
                s3 = fmaf(whh0[k + 12], h0b[k + 12], s3);
            }
            const float h0 = fast_tanh((s0 + s1) + (s2 + s3));

            // ---- layer 1 partial: Whh1[j,:]·h1_prev (independent of h0 — overlaps shfl latency) ----
            float t0 = bh1, t1 = 0.f, t2 = 0.f, t3 = 0.f;
#pragma unroll
            for (int k = 0; k < 4; k++) {
                t0 = fmaf(whh1[k],      h1b[k],      t0);
                t1 = fmaf(whh1[k + 4],  h1b[k + 4],  t1);
                t2 = fmaf(whh1[k + 8],  h1b[k + 8],  t2);
                t3 = fmaf(whh1[k + 12], h1b[k + 12], t3);
            }

            // ---- broadcast h0 (current step) to all lanes of this half-warp ----
#pragma unroll
            for (int k = 0; k < HID; k++)
                h0b[k] = __shfl_sync(FULLMASK, h0, base + k);

            // ---- layer 1 finish: + Wih1[j,:]·h0_cur ----
#pragma unroll
            for (int k = 0; k < 4; k++) {
                t0 = fmaf(wih1[k],      h0b[k],      t0);
                t1 = fmaf(wih1[k + 4],  h0b[k + 4],  t1);
                t2 = fmaf(wih1[k + 8],  h0b[k + 8],  t2);
                t3 = fmaf(wih1[k + 12], h0b[k + 12], t3);
            }
            const float h1 = fast_tanh((t0 + t1) + (t2 + t3));

            // ---- broadcast h1; reused by post-dot NOW and Whh1 NEXT step ----
#pragma unroll
            for (int k = 0; k < HID; k++)
                h1b[k] = __shfl_sync(FULLMASK, h1, base + k);

            // ---- post layer (redundant on all 16 lanes of the half-warp; no reduction needed) ----
            float p0 = fmaf(whhp, y, bp), p1 = 0.f, p2 = 0.f, p3 = 0.f;
#pragma unroll
            for (int k = 0; k < 4; k++) {
                p0 = fmaf(wihp[k],      h1b[k],      p0);
                p1 = fmaf(wihp[k + 4],  h1b[k + 4],  p1);
                p2 = fmaf(wihp[k + 8],  h1b[k + 8],  p2);
                p3 = fmaf(wihp[k + 12], h1b[k + 12], p3);
            }
            y = fast_tanh((p0 + p1) + (p2 + p3));

            if (s == 0) yv.x = y;
            else if (s == 1) yv.y = y;
            else if (s == 2) yv.z = y;
            else yv.w = y;
        }

        // one lane per batch writes 4 timesteps
        if (j == 0) *(float4*)(ob + tc) = yv;
    }
}

extern "C" void kernel_launch(void* const* d_in, const int* in_sizes, int n_in,
                              void* d_out, int out_size)
{
    const float* x       = (const float*)d_in[0];
    const float* prev_h0 = (const float*)d_in[1];
    const float* post_h0 = (const float*)d_in[2];
    const float* W_ih0   = (const float*)d_in[3];
    const float* W_hh0   = (const float*)d_in[4];
    const float* b_ih0   = (const float*)d_in[5];
    const float* b_hh0   = (const float*)d_in[6];
    const float* W_ih1   = (const float*)d_in[7];
    const float* W_hh1   = (const float*)d_in[8];
    const float* b_ih1   = (const float*)d_in[9];
    const float* b_hh1   = (const float*)d_in[10];
    const float* W_ihp   = (const float*)d_in[11];
    const float* W_hhp   = (const float*)d_in[12];
    const float* b_ihp   = (const float*)d_in[13];
    const float* b_hhp   = (const float*)d_in[14];
    float* out = (float*)d_out;

    const int T = in_sizes[0] / BATCH;   // IN == 1

    rnn3_scan_kernel<<<BATCH / 2, 32>>>(
        x, prev_h0, post_h0,
        W_ih0, W_hh0, b_ih0, b_hh0,
        W_ih1, W_hh1, b_ih1, b_hh1,
        W_ihp, W_hhp, b_ihp, b_hhp,
        out, T);
}

// round 3
// speedup vs baseline: 1.1612x; 1.1612x over previous
#include <cuda_runtime.h>
#include <cstdint>

#define FULLMASK 0xFFFFFFFFu
typedef unsigned long long ull;

constexpr int BATCH = 256;
constexpr int HID   = 16;
// 2*log2(e): folded into all weights/biases so tanh(a) = 1 - 2/(1+exp2(a'))
#define TANH_SCALE 2.885390081777927f

// ---- packed f32x2 helpers (Blackwell FFMA2 — only reachable via PTX) ----
__device__ __forceinline__ ull pack2(float lo, float hi) {
    ull r; asm("mov.b64 %0, {%1,%2};" : "=l"(r) : "f"(lo), "f"(hi)); return r;
}
__device__ __forceinline__ void unpack2(ull v, float& lo, float& hi) {
    asm("mov.b64 {%0,%1}, %2;" : "=f"(lo), "=f"(hi) : "l"(v));
}
__device__ __forceinline__ ull fma2(ull a, ull b, ull c) {
    ull d; asm("fma.rn.f32x2 %0, %1, %2, %3;" : "=l"(d) : "l"(a), "l"(b), "l"(c)); return d;
}
__device__ __forceinline__ ull add2(ull a, ull b) {
    ull d; asm("add.rn.f32x2 %0, %1, %2;" : "=l"(d) : "l"(a), "l"(b)); return d;
}

// tanh on a PRE-SCALED argument a' = 2*log2(e)*a:  tanh = 1 - 2/(1+exp2(a'))
__device__ __forceinline__ float tanh_pre(float a) {
    float e; asm("ex2.approx.f32 %0, %1;" : "=f"(e) : "f"(a));
    float r; asm("rcp.approx.f32 %0, %1;" : "=f"(r) : "f"(e + 1.0f));
    return fmaf(-2.0f, r, 1.0f);
}

__global__ void __launch_bounds__(32, 1) rnn3_scan_kernel(
    const float* __restrict__ x,        // [B, T, 1]
    const float* __restrict__ prev_h0,  // [2, 16]
    const float* __restrict__ post_h0,  // [1, 1]
    const float* __restrict__ W_ih0,    // [16, 1]
    const float* __restrict__ W_hh0,    // [16, 16]
    const float* __restrict__ b_ih0,    // [16]
    const float* __restrict__ b_hh0,    // [16]
    const float* __restrict__ W_ih1,    // [16, 16]
    const float* __restrict__ W_hh1,    // [16, 16]
    const float* __restrict__ b_ih1,    // [16]
    const float* __restrict__ b_hh1,    // [16]
    const float* __restrict__ W_ihp,    // [1, 16]
    const float* __restrict__ W_hhp,    // [1, 1]
    const float* __restrict__ b_ihp,    // [1]
    const float* __restrict__ b_hhp,    // [1]
    float* __restrict__ out,            // [B, T, 1]
    int T)
{
    const int lane  = threadIdx.x;      // 0..31
    const int j     = lane & 15;        // hidden unit owned by this lane
    const int base  = lane & 16;        // half-warp base (batch A / batch B)
    const int batch = blockIdx.x * 2 + (lane >> 4);

    const float C = TANH_SCALE;

    // ---- register-resident, pre-scaled, pair-packed weights ----
    ull whh0p[8], wih1p[8], whh1p[8];
#pragma unroll
    for (int k = 0; k < 8; k++) {
        whh0p[k] = pack2(C * __ldg(&W_hh0[j * HID + 2 * k]), C * __ldg(&W_hh0[j * HID + 2 * k + 1]));
        wih1p[k] = pack2(C * __ldg(&W_ih1[j * HID + 2 * k]), C * __ldg(&W_ih1[j * HID + 2 * k + 1]));
        whh1p[k] = pack2(C * __ldg(&W_hh1[j * HID + 2 * k]), C * __ldg(&W_hh1[j * HID + 2 * k + 1]));
    }
    const float wih0C = C * __ldg(&W_ih0[j]);
    const float bh0C  = C * (__ldg(&b_ih0[j]) + __ldg(&b_hh0[j]));
    const float bh1C  = C * (__ldg(&b_ih1[j]) + __ldg(&b_hh1[j]));
    const float wihpC = C * __ldg(&W_ihp[j]);        // own column only (distributed post dot)
    const float whhpC = C * __ldg(&W_hhp[0]);
    const float bpC   = C * (__ldg(&b_ihp[0]) + __ldg(&b_hhp[0]));

    // min-max normalize folded: xn=(x+1)/2 -> wih0C*xn + bh0C = wih0h*x + (bh0C + wih0h)
    const float wih0h = 0.5f * wih0C;
    const float bh0h  = bh0C + wih0h;                // <-- FIX: fold the +wih0h constant
    const ull bias0_2 = pack2(bh0h, 0.0f);           //     into the packed bias (was bh0C)
    const ull bias1_2 = pack2(bh1C, 0.0f);

    // ---- pipeline state ----
    // entering iteration i: h0b2 = h0[i-1], h1b2 = h1[i-2] (packed broadcasts),
    //                       h1d1 = own h1[i-2], y = y[i-3]
    ull h0b2[8], h1b2[8];
#pragma unroll
    for (int k = 0; k < 8; k++) {
        h0b2[k] = pack2(__ldg(&prev_h0[2 * k]),       __ldg(&prev_h0[2 * k + 1]));
        h1b2[k] = pack2(__ldg(&prev_h0[HID + 2 * k]), __ldg(&prev_h0[HID + 2 * k + 1]));
    }
    float h1d1 = __ldg(&prev_h0[HID + j]);
    float y    = __ldg(&post_h0[0]);

    const float* xb = x   + (size_t)batch * T;
    float*       ob = out + (size_t)batch * T;

    // ---- stage helpers ----
    auto sdot_tanh = [&](float xt) -> float {          // layer 0: reads h0b2
        ull s0 = fma2(whh0p[0], h0b2[0], bias0_2);
        ull s1 = fma2(whh0p[4], h0b2[4], 0ULL);
#pragma unroll
        for (int k = 1; k < 4; k++) {
            s0 = fma2(whh0p[k],     h0b2[k],     s0);
            s1 = fma2(whh0p[4 + k], h0b2[4 + k], s1);
        }
        ull ss = add2(s0, s1);
        float lo, hi; unpack2(ss, lo, hi);
        return tanh_pre(fmaf(wih0h, xt, lo + hi));
    };
    auto tdot_tanh = [&]() -> float {                   // layer 1: reads h0b2, h1b2
        ull t0 = fma2(wih1p[0], h0b2[0], bias1_2);
        ull t1 = fma2(wih1p[4], h0b2[4], 0ULL);
#pragma unroll
        for (int k = 1; k < 4; k++) {
            t0 = fma2(wih1p[k],     h0b2[k],     t0);
            t1 = fma2(wih1p[4 + k], h0b2[4 + k], t1);
        }
#pragma unroll
        for (int k = 0; k < 4; k++) {
            t0 = fma2(whh1p[k],     h1b2[k],     t0);
            t1 = fma2(whh1p[4 + k], h1b2[4 + k], t1);
        }
        ull tt = add2(t0, t1);
        float lo, hi; unpack2(tt, lo, hi);
        return tanh_pre(lo + hi);
    };
    auto pdot_tanh = [&]() -> float {                   // post: distributed over half-warp
        float pr = wihpC * h1d1;
        pr += __shfl_xor_sync(FULLMASK, pr, 1);
        pr += __shfl_xor_sync(FULLMASK, pr, 2);
        pr += __shfl_xor_sync(FULLMASK, pr, 4);
        pr += __shfl_xor_sync(FULLMASK, pr, 8);
        return tanh_pre(pr + fmaf(whhpC, y, bpC));
    };
    auto bcast0 = [&](float h0n) {
#pragma unroll
        for (int k = 0; k < 8; k++)
            h0b2[k] = pack2(__shfl_sync(FULLMASK, h0n, base + 2 * k),
                            __shfl_sync(FULLMASK, h0n, base + 2 * k + 1));
    };
    auto bcast1 = [&](float h1n) {
#pragma unroll
        for (int k = 0; k < 8; k++)
            h1b2[k] = pack2(__shfl_sync(FULLMASK, h1n, base + 2 * k),
                            __shfl_sync(FULLMASK, h1n, base + 2 * k + 1));
    };

    // ---- prologue: peel i = 0 and i = 1 ----
    {   // i = 0: layer0 only -> h0[0]
        float h0n = sdot_tanh(xb[0]);
        bcast0(h0n);
    }
    {   // i = 1: layer0 -> h0[1]; layer1 -> h1[0]
        float h0n = sdot_tanh(xb[1]);
        float h1n = tdot_tanh();
        bcast0(h0n);
        bcast1(h1n);
        h1d1 = h1n;
    }

    // ---- x prefetch pipeline (4-deep) ----
    float xq0 = xb[2], xq1 = (3 < T ? xb[3] : 0.f),
          xq2 = (4 < T ? xb[4] : 0.f), xq3 = (5 < T ? xb[5] : 0.f);

    // ---- main loop: iteration i computes h0[i], h1[i-1], y[i-2] ----
#pragma unroll 4
    for (int i = 2; i < T; i++) {
        const float xt = xq0;
        xq0 = xq1; xq1 = xq2; xq2 = xq3;
        xq3 = (i + 4 < T) ? xb[i + 4] : 0.0f;

        float h0n = sdot_tanh(xt);    // -> h0[i]
        float h1n = tdot_tanh();      // -> h1[i-1]   (reads pre-update h0b2,h1b2)
        float yn  = pdot_tanh();      // -> y[i-2]    (reads h1d1, y)

        bcast0(h0n);
        bcast1(h1n);
        h1d1 = h1n;
        y    = yn;
        if (j == 0) ob[i - 2] = yn;
    }

    // ---- epilogue: i = T (layer1 + post), i = T+1 (post) ----
    {   // i = T: h1[T-1], y[T-2]
        float h1n = tdot_tanh();
        float yn  = pdot_tanh();
        h1d1 = h1n;
        y    = yn;
        if (j == 0) ob[T - 2] = yn;
    }
    {   // i = T+1: y[T-1]
        float yn = pdot_tanh();
        if (j == 0) ob[T - 1] = yn;
    }
}

extern "C" void kernel_launch(void* const* d_in, const int* in_sizes, int n_in,
                              void* d_out, int out_size)
{
    const float* x       = (const float*)d_in[0];
    const float* prev_h0 = (const float*)d_in[1];
    const float* post_h0 = (const float*)d_in[2];
    const float* W_ih0   = (const float*)d_in[3];
    const float* W_hh0   = (const float*)d_in[4];
    const float* b_ih0   = (const float*)d_in[5];
    const float* b_hh0   = (const float*)d_in[6];
    const float* W_ih1   = (const float*)d_in[7];
    const float* W_hh1   = (const float*)d_in[8];
    const float* b_ih1   = (const float*)d_in[9];
    const float* b_hh1   = (const float*)d_in[10];
    const float* W_ihp   = (const float*)d_in[11];
    const float* W_hhp   = (const float*)d_in[12];
    const float* b_ihp   = (const float*)d_in[13];
    const float* b_hhp   = (const float*)d_in[14];
    float* out = (float*)d_out;

    const int T = in_sizes[0] / BATCH;   // IN == 1

    rnn3_scan_kernel<<<BATCH / 2, 32>>>(
        x, prev_h0, post_h0,
        W_ih0, W_hh0, b_ih0, b_hh0,
        W_ih1, W_hh1, b_ih1, b_hh1,
        W_ihp, W_hhp, b_ihp, b_hhp,
        out, T);
}

// round 4
// speedup vs baseline: 1.5669x; 1.3494x over previous
#include <cuda_runtime.h>
#include <cstdint>

#define FULLMASK 0xFFFFFFFFu
typedef unsigned long long ull;

constexpr int BATCH = 256;
constexpr int HID   = 16;
// 2*log2(e): folded into all weights/biases so tanh(a) = 1 - 2/(1+exp2(a'))
#define TANH_SCALE 2.885390081777927f

// ---- packed f32x2 helpers (Blackwell FFMA2 — only reachable via PTX) ----
__device__ __forceinline__ ull pack2(float lo, float hi) {
    ull r; asm("mov.b64 %0, {%1,%2};" : "=l"(r) : "f"(lo), "f"(hi)); return r;
}
__device__ __forceinline__ void unpack2(ull v, float& lo, float& hi) {
    asm("mov.b64 {%0,%1}, %2;" : "=f"(lo), "=f"(hi) : "l"(v));
}
__device__ __forceinline__ ull fma2(ull a, ull b, ull c) {
    ull d; asm("fma.rn.f32x2 %0, %1, %2, %3;" : "=l"(d) : "l"(a), "l"(b), "l"(c)); return d;
}
__device__ __forceinline__ ull add2(ull a, ull b) {
    ull d; asm("add.rn.f32x2 %0, %1, %2;" : "=l"(d) : "l"(a), "l"(b)); return d;
}

// tanh on a PRE-SCALED argument a' = 2*log2(e)*a:  tanh = 1 - 2/(1+exp2(a'))
__device__ __forceinline__ float tanh_pre(float a) {
    float e; asm("ex2.approx.f32 %0, %1;" : "=f"(e) : "f"(a));
    float r; asm("rcp.approx.f32 %0, %1;" : "=f"(r) : "f"(e + 1.0f));
    return fmaf(-2.0f, r, 1.0f);
}

__global__ void __launch_bounds__(32, 1) rnn3_scan_kernel(
    const float* __restrict__ x,        // [B, T, 1]
    const float* __restrict__ prev_h0,  // [2, 16]
    const float* __restrict__ post_h0,  // [1, 1]
    const float* __restrict__ W_ih0,    // [16, 1]
    const float* __restrict__ W_hh0,    // [16, 16]
    const float* __restrict__ b_ih0,    // [16]
    const float* __restrict__ b_hh0,    // [16]
    const float* __restrict__ W_ih1,    // [16, 16]
    const float* __restrict__ W_hh1,    // [16, 16]
    const float* __restrict__ b_ih1,    // [16]
    const float* __restrict__ b_hh1,    // [16]
    const float* __restrict__ W_ihp,    // [1, 16]
    const float* __restrict__ W_hhp,    // [1, 1]
    const float* __restrict__ b_ihp,    // [1]
    const float* __restrict__ b_hhp,    // [1]
    float* __restrict__ out,            // [B, T, 1]
    int T)
{
    const int lane = threadIdx.x;       // 0..31
    const int j    = lane & 15;         // hidden unit owned by this lane
    const int half = lane >> 4;         // 0 = batch A, 1 = batch B
    const int batch = blockIdx.x * 2 + half;

    // smem broadcast buffers: [slot][batch-half][16 floats]
    // STS: 32 lanes hit 32 distinct banks. LDS.128: two broadcast address
    // groups (half 0 / half 1) touching disjoint banks -> conflict-free.
    __shared__ __align__(16) float SH0[2][2][16];
    __shared__ __align__(16) float SH1[2][2][16];

    const float C = TANH_SCALE;

    // ---- register-resident, pre-scaled, pair-packed weights ----
    ull whh0p[8], wih1p[8], whh1p[8], wihpp[8];
#pragma unroll
    for (int k = 0; k < 8; k++) {
        whh0p[k] = pack2(C * __ldg(&W_hh0[j * HID + 2 * k]), C * __ldg(&W_hh0[j * HID + 2 * k + 1]));
        wih1p[k] = pack2(C * __ldg(&W_ih1[j * HID + 2 * k]), C * __ldg(&W_ih1[j * HID + 2 * k + 1]));
        whh1p[k] = pack2(C * __ldg(&W_hh1[j * HID + 2 * k]), C * __ldg(&W_hh1[j * HID + 2 * k + 1]));
        wihpp[k] = pack2(C * __ldg(&W_ihp[2 * k]),           C * __ldg(&W_ihp[2 * k + 1]));
    }
    const float wih0C = C * __ldg(&W_ih0[j]);
    const float bh0C  = C * (__ldg(&b_ih0[j]) + __ldg(&b_hh0[j]));
    const float bh1C  = C * (__ldg(&b_ih1[j]) + __ldg(&b_hh1[j]));
    const float whhpC = C * __ldg(&W_hhp[0]);
    const float bpC   = C * (__ldg(&b_ihp[0]) + __ldg(&b_hhp[0]));

    // min-max normalize folded: xn=(x+1)/2 -> wih0C*xn + bh0C = wih0h*x + bh0h
    const float wih0h = 0.5f * wih0C;
    const float bh0h  = bh0C + wih0h;
    const ull bias1_2 = pack2(bh1C, 0.0f);

    // ---- pipeline state: entering iter i, h0p = h0[i-1], h1p = h1[i-2], y = y[i-3]
    ull h0p[8], h1p[8];
#pragma unroll
    for (int k = 0; k < 8; k++) {
        h0p[k] = pack2(__ldg(&prev_h0[2 * k]),       __ldg(&prev_h0[2 * k + 1]));
        h1p[k] = pack2(__ldg(&prev_h0[HID + 2 * k]), __ldg(&prev_h0[HID + 2 * k + 1]));
    }
    float y = __ldg(&post_h0[0]);

    const float* xb = x   + (size_t)batch * T;
    float*       ob = out + (size_t)batch * T;

    // ---- stage helpers ----
    auto sdot_tanh = [&](float xt) -> float {          // layer 0: reads h0p
        const float xterm = fmaf(wih0h, xt, bh0h);     // off the LDS->fma chain
        ull s0 = fma2(whh0p[0], h0p[0], pack2(xterm, 0.0f));
        ull s1 = fma2(whh0p[4], h0p[4], 0ULL);
#pragma unroll
        for (int k = 1; k < 4; k++) {
            s0 = fma2(whh0p[k],     h0p[k],     s0);
            s1 = fma2(whh0p[4 + k], h0p[4 + k], s1);
        }
        ull ss = add2(s0, s1);
        float lo, hi; unpack2(ss, lo, hi);
        return tanh_pre(lo + hi);
    };
    auto tdot_tanh = [&]() -> float {                   // layer 1: reads h0p, h1p (4 chains of 4)
        ull t0 = fma2(wih1p[0], h0p[0], bias1_2);
        ull t1 = fma2(wih1p[4], h0p[4], 0ULL);
        ull t2 = fma2(whh1p[0], h1p[0], 0ULL);
        ull t3 = fma2(whh1p[4], h1p[4], 0ULL);
#pragma unroll
        for (int k = 1; k < 4; k++) {
            t0 = fma2(wih1p[k],     h0p[k],     t0);
            t1 = fma2(wih1p[4 + k], h0p[4 + k], t1);
            t2 = fma2(whh1p[k],     h1p[k],     t2);
            t3 = fma2(whh1p[4 + k], h1p[4 + k], t3);
        }
        ull tt = add2(add2(t0, t1), add2(t2, t3));
        float lo, hi; unpack2(tt, lo, hi);
        return tanh_pre(lo + hi);
    };
    auto pdot_tanh = [&]() -> float {                   // post: packed redundant dot on h1p
        ull q0 = fma2(wihpp[0], h1p[0], 0ULL);
        ull q1 = fma2(wihpp[4], h1p[4], 0ULL);
#pragma unroll
        for (int k = 1; k < 4; k++) {
            q0 = fma2(wihpp[k],     h1p[k],     q0);
            q1 = fma2(wihpp[4 + k], h1p[4 + k], q1);
        }
        ull qq = add2(q0, q1);
        float lo, hi; unpack2(qq, lo, hi);
        return tanh_pre((lo + hi) + fmaf(whhpC, y, bpC));
    };
    auto ldp = [&](ull* dst, float (*arr)[2][16], int slot) {
        const ulonglong2* p = (const ulonglong2*)(arr[slot][half]);
        ulonglong2 a = p[0], b = p[1], c = p[2], d = p[3];
        dst[0] = a.x; dst[1] = a.y; dst[2] = b.x; dst[3] = b.y;
        dst[4] = c.x; dst[5] = c.y; dst[6] = d.x; dst[7] = d.y;
    };

    float yq0 = 0.f, yq1 = 0.f, yq2 = 0.f, yq3 = 0.f;

    // ---- prologue: i = 0, 1 (pipeline fill), i = 2, 3 (alignment peel) ----
    {
        const float4 x03 = *(const float4*)xb;   // x[0..3]
        {   // i = 0: h0[0]
            float h0n = sdot_tanh(x03.x);
            SH0[0][half][j] = h0n;
            __syncwarp();
            ldp(h0p, SH0, 0);
        }
        {   // i = 1: h0[1], h1[0]
            float h0n = sdot_tanh(x03.y);
            float h1n = tdot_tanh();
            SH0[1][half][j] = h0n;
            SH1[1][half][j] = h1n;
            __syncwarp();
            ldp(h0p, SH0, 1);
            ldp(h1p, SH1, 1);
        }
        {   // i = 2: h0[2], h1[1], y[0]
            float h0n = sdot_tanh(x03.z);
            float h1n = tdot_tanh();
            float yn  = pdot_tanh();
            SH0[0][half][j] = h0n;
            SH1[0][half][j] = h1n;
            __syncwarp();
            ldp(h0p, SH0, 0);
            ldp(h1p, SH1, 0);
            y = yn; yq0 = yn;
        }
        {   // i = 3: h0[3], h1[2], y[1]
            float h0n = sdot_tanh(x03.w);
            float h1n = tdot_tanh();
            float yn  = pdot_tanh();
            SH0[1][half][j] = h0n;
            SH1[1][half][j] = h1n;
            __syncwarp();
            ldp(h0p, SH0, 1);
            ldp(h1p, SH1, 1);
            y = yn; yq1 = yn;
        }
    }

    // ---- x prefetch: aligned float4, 2-deep ----
    const float4* X = (const float4*)xb;
    float4 xcur = X[1];                       // x[4..7]
    float4 xnxt = X[2];                       // x[8..11]

    // ---- main loop: tc = 4 .. T-4 step 4; iter i = tc+s computes h0[i], h1[i-1], y[i-2] ----
    for (int tc = 4; tc < T; tc += 4) {
#pragma unroll
        for (int s = 0; s < 4; s++) {
            const int slot = s & 1;           // tc is even
            const float xt = (s == 0) ? xcur.x : (s == 1) ? xcur.y : (s == 2) ? xcur.z : xcur.w;

            float h0n = sdot_tanh(xt);        // -> h0[i]
            float h1n = tdot_tanh();          // -> h1[i-1]  (old h0p,h1p)
            float yn  = pdot_tanh();          // -> y[i-2]   (old h1p, y)

            SH0[slot][half][j] = h0n;
            SH1[slot][half][j] = h1n;
            __syncwarp();
            ldp(h0p, SH0, slot);
            ldp(h1p, SH1, slot);
            y = yn;

            // y[i-2] lands at queue position (s+2)&3
            if (s == 0) yq2 = yn;
            else if (s == 1) {
                yq3 = yn;
                if (j == 0) *(float4*)(ob + tc - 4) = make_float4(yq0, yq1, yq2, yq3);
            }
            else if (s == 2) yq0 = yn;
            else yq1 = yn;
        }
        xcur = xnxt;
        xnxt = (tc + 8 < T) ? X[tc / 4 + 2] : xnxt;
    }

    // ---- epilogue: i = T (h1[T-1], y[T-2]), i = T+1 (y[T-1]) ----
    {
        float h1n = tdot_tanh();
        float yn  = pdot_tanh();
        SH1[0][half][j] = h1n;
        __syncwarp();
        ldp(h1p, SH1, 0);
        y = yn; yq2 = yn;
    }
    {
        float yn = pdot_tanh();
        yq3 = yn;
        if (j == 0) *(float4*)(ob + T - 4) = make_float4(yq0, yq1, yq2, yq3);
    }
}

extern "C" void kernel_launch(void* const* d_in, const int* in_sizes, int n_in,
                              void* d_out, int out_size)
{
    const float* x       = (const float*)d_in[0];
    const float* prev_h0 = (const float*)d_in[1];
    const float* post_h0 = (const float*)d_in[2];
    const float* W_ih0   = (const float*)d_in[3];
    const float* W_hh0   = (const float*)d_in[4];
    const float* b_ih0   = (const float*)d_in[5];
    const float* b_hh0   = (const float*)d_in[6];
    const float* W_ih1   = (const float*)d_in[7];
    const float* W_hh1   = (const float*)d_in[8];
    const float* b_ih1   = (const float*)d_in[9];
    const float* b_hh1   = (const float*)d_in[10];
    const float* W_ihp   = (const float*)d_in[11];
    const float* W_hhp   = (const float*)d_in[12];
    const float* b_ihp   = (const float*)d_in[13];
    const float* b_hhp   = (const float*)d_in[14];
    float* out = (float*)d_out;

    const int T = in_sizes[0] / BATCH;   // IN == 1, T = 16384 (multiple of 4)

    rnn3_scan_kernel<<<BATCH / 2, 32>>>(
        x, prev_h0, post_h0,
        W_ih0, W_hh0, b_ih0, b_hh0,
        W_ih1, W_hh1, b_ih1, b_hh1,
        W_ihp, W_hhp, b_ihp, b_hhp,
        out, T);
}